// round 2
// baseline (speedup 1.0000x reference)
#include <cuda_runtime.h>
#include <cstddef>

#define BB 4
#define NN 8192
#define CC 128
#define SS 2048
#define KK 32
#define PT 8   // points per thread in FPS (1024 threads * 8 = 8192)

__device__ int g_fps_idx[BB * SS];

// ---------------------------------------------------------------------------
// FPS: one CTA per batch. xyz + running dist live in registers; a shared SoA
// copy of xyz exists only so the winning centroid can be fetched by index.
// Exactly replicates reference numerics (verified exact in R1):
//   d = ((dx*dx + dy*dy) + dz*dz) with unfused rn ops; dist = min(dist, d);
//   argmax = first index of maximum.
// ---------------------------------------------------------------------------
__global__ __launch_bounds__(1024, 1) void fps_kernel(const float* __restrict__ xyz)
{
    const int b = blockIdx.x;
    const int t = threadIdx.x;

    extern __shared__ float sh[];
    float* sx = sh;
    float* sy = sh + NN;
    float* sz = sh + 2 * NN;

    __shared__ float rv[32];
    __shared__ int   ri[32];
    __shared__ int   s_far;

    const float* base = xyz + (size_t)b * NN * 3;

    float px[PT], py[PT], pz[PT], pd[PT];
#pragma unroll
    for (int j = 0; j < PT; j++) {
        const int i = t * PT + j;
        const float x = base[i * 3 + 0];
        const float y = base[i * 3 + 1];
        const float z = base[i * 3 + 2];
        px[j] = x; py[j] = y; pz[j] = z;
        pd[j] = 1e10f;
        sx[i] = x; sy[i] = y; sz[i] = z;
    }
    if (t == 0) g_fps_idx[b * SS + 0] = 0;
    __syncthreads();

    int far = 0;
    const int lane = t & 31;
    const int w = t >> 5;

    for (int step = 1; step < SS; ++step) {
        const float cx = sx[far];
        const float cy = sy[far];
        const float cz = sz[far];

        float bv = -1.0f;
        int   bi = 0;
#pragma unroll
        for (int j = 0; j < PT; j++) {
            const float dx = __fsub_rn(px[j], cx);
            const float dy = __fsub_rn(py[j], cy);
            const float dz = __fsub_rn(pz[j], cz);
            const float d  = __fadd_rn(__fadd_rn(__fmul_rn(dx, dx), __fmul_rn(dy, dy)),
                                       __fmul_rn(dz, dz));
            const float nd = fminf(pd[j], d);
            pd[j] = nd;
            if (nd > bv) { bv = nd; bi = t * PT + j; }   // strict >: keeps first max
        }

        // warp argmax (equal value -> smaller index)
#pragma unroll
        for (int off = 16; off > 0; off >>= 1) {
            const float ov = __shfl_down_sync(0xffffffffu, bv, off);
            const int   oi = __shfl_down_sync(0xffffffffu, bi, off);
            if (ov > bv || (ov == bv && oi < bi)) { bv = ov; bi = oi; }
        }
        if (lane == 0) { rv[w] = bv; ri[w] = bi; }
        __syncthreads();

        if (w == 0) {
            float v2 = rv[lane];
            int   i2 = ri[lane];
#pragma unroll
            for (int off = 16; off > 0; off >>= 1) {
                const float ov = __shfl_down_sync(0xffffffffu, v2, off);
                const int   oi = __shfl_down_sync(0xffffffffu, i2, off);
                if (ov > v2 || (ov == v2 && oi < i2)) { v2 = ov; i2 = oi; }
            }
            if (lane == 0) {
                s_far = i2;
                g_fps_idx[b * SS + step] = i2;
            }
        }
        __syncthreads();
        far = s_far;
    }
}

// ---------------------------------------------------------------------------
// Fused ball query + grouping + affine + channel max.
// One block per (s, b) query, 128 threads.
// R2 change: the dot product q.x is computed as a cublas-style FMA chain
// from zero (acc = fma(q2,x2, fma(q1,x1, rn(q0*x0)))) to match the
// reference's einsum/GEMM accumulation rounding exactly.
// x2 / q2 stay as unfused elementwise-square + sequential reduce (matches
// XLA's jnp.sum(x*x) lowering).
// ---------------------------------------------------------------------------
__global__ __launch_bounds__(128) void group_kernel(
    const float* __restrict__ xyz,
    const float* __restrict__ points,
    const float* __restrict__ alpha,
    const float* __restrict__ beta,
    float* __restrict__ out_xyz,
    float* __restrict__ out_pts)
{
    const int s = blockIdx.x;
    const int b = blockIdx.y;
    const int tid = threadIdx.x;

    __shared__ int   s_nbr[KK];
    __shared__ int   s_wc[4];
    __shared__ float s_q[3];

    const int fi = g_fps_idx[b * SS + s];
    const float* xb = xyz + (size_t)b * NN * 3;

    if (tid == 0) {
        s_q[0] = xb[fi * 3 + 0];
        s_q[1] = xb[fi * 3 + 1];
        s_q[2] = xb[fi * 3 + 2];
    }
    __syncthreads();

    const float qx = s_q[0], qy = s_q[1], qz = s_q[2];
    const float q2 = __fadd_rn(__fadd_rn(__fmul_rn(qx, qx), __fmul_rn(qy, qy)),
                               __fmul_rn(qz, qz));
    const float RR = 0.04f;   // f32(0.2 * 0.2)

    int cnt = 0;
    const int lane = tid & 31;
    const int w = tid >> 5;

    for (int base2 = 0; base2 < NN && cnt < KK; base2 += 128) {
        const int i = base2 + tid;
        const float xx = xb[i * 3 + 0];
        const float xy = xb[i * 3 + 1];
        const float xz = xb[i * 3 + 2];
        const float x2 = __fadd_rn(__fadd_rn(__fmul_rn(xx, xx), __fmul_rn(xy, xy)),
                                   __fmul_rn(xz, xz));
        // GEMM-style fma-chain dot (k-order 0,1,2, acc starts at 0):
        const float dt = __fmaf_rn(qz, xz, __fmaf_rn(qy, xy, __fmul_rn(qx, xx)));
        const float sqr = __fsub_rn(__fadd_rn(q2, x2), __fmul_rn(2.0f, dt));
        const bool hit = (sqr <= RR);

        const unsigned m = __ballot_sync(0xffffffffu, hit);
        if (lane == 0) s_wc[w] = __popc(m);
        __syncthreads();

        int before = cnt;
        for (int ww = 0; ww < w; ww++) before += s_wc[ww];
        const int pos = before + __popc(m & ((1u << lane) - 1u));
        if (hit && pos < KK) s_nbr[pos] = i;
        const int tot = s_wc[0] + s_wc[1] + s_wc[2] + s_wc[3];
        __syncthreads();
        cnt += tot;   // uniform across block
    }

    const int cf = (cnt < KK) ? cnt : KK;
    if (tid >= cf && tid < KK) s_nbr[tid] = s_nbr[0];   // pad with first hit
    __syncthreads();

    if (tid < 3) out_xyz[((size_t)b * SS + s) * 3 + tid] = s_q[tid];

    const int c = tid;
    const float a  = alpha[c];
    const float bt = beta[c];
    const float* pb = points + (size_t)b * NN * CC;
    const float anc = pb[(size_t)fi * CC + c];

    float mx = -3.402823466e38f;
#pragma unroll 8
    for (int k = 0; k < KK; k++) {
        const float v = pb[(size_t)s_nbr[k] * CC + c];
        const float g = __fadd_rn(__fmul_rn(a, __fsub_rn(v, anc)), bt);
        mx = fmaxf(mx, g);
    }
    out_pts[((size_t)b * CC + c) * SS + s] = mx;
}

// ---------------------------------------------------------------------------
// Output layout: new_xyz (B,S,3) flat, then new_points (B,C,S) flat.
// ---------------------------------------------------------------------------
extern "C" void kernel_launch(void* const* d_in, const int* in_sizes, int n_in,
                              void* d_out, int out_size)
{
    const float* xyz    = (const float*)d_in[0];
    const float* points = (const float*)d_in[1];
    const float* alpha  = (const float*)d_in[2];
    const float* beta   = (const float*)d_in[3];

    float* out     = (float*)d_out;
    float* out_xyz = out;
    float* out_pts = out + (size_t)BB * SS * 3;

    cudaFuncSetAttribute(fps_kernel, cudaFuncAttributeMaxDynamicSharedMemorySize,
                         3 * NN * (int)sizeof(float));
    fps_kernel<<<BB, 1024, 3 * NN * sizeof(float)>>>(xyz);
    group_kernel<<<dim3(SS, BB), 128>>>(xyz, points, alpha, beta, out_xyz, out_pts);
}

// round 3
// speedup vs baseline: 1.7849x; 1.7849x over previous
#include <cuda_runtime.h>
#include <cstddef>

#define BB 4
#define NN 8192
#define CC 128
#define SS 2048
#define KK 32
#define FT 512          // FPS threads
#define PT 16           // points per thread (512*16 = 8192)
#define NPAIR (PT/2)

typedef unsigned long long u64;

__device__ int g_fps_idx[BB * SS];

// ---- packed f32x2 helpers (each half is an independent IEEE f32 rn op) ----
__device__ __forceinline__ u64 f2add(u64 a, u64 b) {
    u64 d; asm("add.rn.f32x2 %0, %1, %2;" : "=l"(d) : "l"(a), "l"(b)); return d;
}
__device__ __forceinline__ u64 f2mul(u64 a, u64 b) {
    u64 d; asm("mul.rn.f32x2 %0, %1, %2;" : "=l"(d) : "l"(a), "l"(b)); return d;
}
__device__ __forceinline__ u64 f2pack(float lo, float hi) {
    u64 d; asm("mov.b64 %0, {%1, %2};" : "=l"(d) : "f"(lo), "f"(hi)); return d;
}
__device__ __forceinline__ void f2unpack(u64 v, float& lo, float& hi) {
    asm("mov.b64 {%0, %1}, %2;" : "=f"(lo), "=f"(hi) : "l"(v));
}

// ---------------------------------------------------------------------------
// FPS: one CTA per batch, 512 threads, 16 points/thread register-resident.
// Distance update uses packed f32x2 (bit-exact to the unfused scalar form:
// d = ((dx*dx + dy*dy) + dz*dz), dx = px + (-cx)).
// Argmax: thread scan (first index of max) -> warp REDUX on float bits
// (monotone, dist >= 0) + ballot/ffs (lowest lane = smallest index) ->
// double-buffered shared stage, every warp reduces the 16 warp keys itself.
// ONE __syncthreads per step.
// ---------------------------------------------------------------------------
__global__ __launch_bounds__(FT, 1) void fps_kernel(const float* __restrict__ xyz)
{
    const int b = blockIdx.x;
    const int t = threadIdx.x;
    const int lane = t & 31;
    const int w = t >> 5;

    extern __shared__ float sh[];
    float* sx = sh;
    float* sy = sh + NN;
    float* sz = sh + 2 * NN;

    __shared__ u64 rk[2][16];   // per-warp (valuebits<<32 | index), double-buffered

    const float* base = xyz + (size_t)b * NN * 3;

    u64 pX[NPAIR], pY[NPAIR], pZ[NPAIR];
    float pd[PT];

#pragma unroll
    for (int j = 0; j < PT; j++) {
        const int i = t * PT + j;
        const float x = base[i * 3 + 0];
        const float y = base[i * 3 + 1];
        const float z = base[i * 3 + 2];
        sx[i] = x; sy[i] = y; sz[i] = z;
        pd[j] = 1e10f;
        if (j & 1) {
            float plx, ply, plz, dummy;
            f2unpack(pX[j >> 1], plx, dummy);  // placeholder, replaced below
        }
    }
    // pack (re-read from shared to keep the loop above simple for the compiler)
#pragma unroll
    for (int jp = 0; jp < NPAIR; jp++) {
        const int i0 = t * PT + 2 * jp;
        pX[jp] = f2pack(sx[i0], sx[i0 + 1]);
        pY[jp] = f2pack(sy[i0], sy[i0 + 1]);
        pZ[jp] = f2pack(sz[i0], sz[i0 + 1]);
    }
    if (t == 0) g_fps_idx[b * SS + 0] = 0;
    __syncthreads();

    int far = 0;
    int p = 0;

    for (int step = 1; step < SS; ++step) {
        const float cx = sx[far];
        const float cy = sy[far];
        const float cz = sz[far];
        const u64 ncx = f2pack(-cx, -cx);
        const u64 ncy = f2pack(-cy, -cy);
        const u64 ncz = f2pack(-cz, -cz);

        float tv = 0.0f;   // distances are >= 0
#pragma unroll
        for (int jp = 0; jp < NPAIR; jp++) {
            const u64 dx = f2add(pX[jp], ncx);
            const u64 dy = f2add(pY[jp], ncy);
            const u64 dz = f2add(pZ[jp], ncz);
            const u64 xx = f2mul(dx, dx);
            const u64 yy = f2mul(dy, dy);
            const u64 zz = f2mul(dz, dz);
            const u64 d  = f2add(f2add(xx, yy), zz);
            float dlo, dhi;
            f2unpack(d, dlo, dhi);
            pd[2 * jp]     = fminf(pd[2 * jp],     dlo);
            pd[2 * jp + 1] = fminf(pd[2 * jp + 1], dhi);
            tv = fmaxf(tv, pd[2 * jp]);
            tv = fmaxf(tv, pd[2 * jp + 1]);
        }

        // first local index equal to the max (descending scan -> smallest j wins)
        int bi = t * PT;
#pragma unroll
        for (int j = PT - 1; j >= 0; j--)
            if (pd[j] == tv) bi = t * PT + j;

        // warp argmax via redux on bits (monotone for non-negative floats)
        const unsigned vb = __float_as_uint(tv);
        const unsigned wm = __reduce_max_sync(0xffffffffu, vb);
        const unsigned mk = __ballot_sync(0xffffffffu, vb == wm);
        const int src = __ffs(mk) - 1;            // lowest lane = smallest index
        const int wbi = __shfl_sync(0xffffffffu, bi, src);
        if (lane == 0) rk[p][w] = ((u64)wm << 32) | (unsigned)wbi;
        __syncthreads();

        // every warp reduces the 16 warp keys (no second barrier needed:
        // next write goes to the other buffer, and the write after that is
        // separated from this read by the next step's barrier)
        const u64 k = (lane < 16) ? rk[p][lane] : 0ull;
        const unsigned vb2 = (unsigned)(k >> 32);
        const unsigned wm2 = __reduce_max_sync(0xffffffffu, vb2);
        const unsigned mk2 = __ballot_sync(0xffffffffu, vb2 == wm2);
        const int src2 = __ffs(mk2) - 1;          // lowest warp = smallest index
        far = __shfl_sync(0xffffffffu, (int)(unsigned)k, src2);

        if (t == 0) g_fps_idx[b * SS + step] = far;
        p ^= 1;
    }
}

// ---------------------------------------------------------------------------
// Fused ball query + grouping + affine + channel max (unchanged from R2,
// verified bit-exact).
// ---------------------------------------------------------------------------
__global__ __launch_bounds__(128) void group_kernel(
    const float* __restrict__ xyz,
    const float* __restrict__ points,
    const float* __restrict__ alpha,
    const float* __restrict__ beta,
    float* __restrict__ out_xyz,
    float* __restrict__ out_pts)
{
    const int s = blockIdx.x;
    const int b = blockIdx.y;
    const int tid = threadIdx.x;

    __shared__ int   s_nbr[KK];
    __shared__ int   s_wc[4];
    __shared__ float s_q[3];

    const int fi = g_fps_idx[b * SS + s];
    const float* xb = xyz + (size_t)b * NN * 3;

    if (tid == 0) {
        s_q[0] = xb[fi * 3 + 0];
        s_q[1] = xb[fi * 3 + 1];
        s_q[2] = xb[fi * 3 + 2];
    }
    __syncthreads();

    const float qx = s_q[0], qy = s_q[1], qz = s_q[2];
    const float q2 = __fadd_rn(__fadd_rn(__fmul_rn(qx, qx), __fmul_rn(qy, qy)),
                               __fmul_rn(qz, qz));
    const float RR = 0.04f;   // f32(0.2 * 0.2)

    int cnt = 0;
    const int lane = tid & 31;
    const int w = tid >> 5;

    for (int base2 = 0; base2 < NN && cnt < KK; base2 += 128) {
        const int i = base2 + tid;
        const float xx = xb[i * 3 + 0];
        const float xy = xb[i * 3 + 1];
        const float xz = xb[i * 3 + 2];
        const float x2 = __fadd_rn(__fadd_rn(__fmul_rn(xx, xx), __fmul_rn(xy, xy)),
                                   __fmul_rn(xz, xz));
        // GEMM-style fma-chain dot (k-order 0,1,2, acc starts at 0):
        const float dt = __fmaf_rn(qz, xz, __fmaf_rn(qy, xy, __fmul_rn(qx, xx)));
        const float sqr = __fsub_rn(__fadd_rn(q2, x2), __fmul_rn(2.0f, dt));
        const bool hit = (sqr <= RR);

        const unsigned m = __ballot_sync(0xffffffffu, hit);
        if (lane == 0) s_wc[w] = __popc(m);
        __syncthreads();

        int before = cnt;
        for (int ww = 0; ww < w; ww++) before += s_wc[ww];
        const int pos = before + __popc(m & ((1u << lane) - 1u));
        if (hit && pos < KK) s_nbr[pos] = i;
        const int tot = s_wc[0] + s_wc[1] + s_wc[2] + s_wc[3];
        __syncthreads();
        cnt += tot;   // uniform across block
    }

    const int cf = (cnt < KK) ? cnt : KK;
    if (tid >= cf && tid < KK) s_nbr[tid] = s_nbr[0];   // pad with first hit
    __syncthreads();

    if (tid < 3) out_xyz[((size_t)b * SS + s) * 3 + tid] = s_q[tid];

    const int c = tid;
    const float a  = alpha[c];
    const float bt = beta[c];
    const float* pb = points + (size_t)b * NN * CC;
    const float anc = pb[(size_t)fi * CC + c];

    float mx = -3.402823466e38f;
#pragma unroll 8
    for (int k = 0; k < KK; k++) {
        const float v = pb[(size_t)s_nbr[k] * CC + c];
        const float g = __fadd_rn(__fmul_rn(a, __fsub_rn(v, anc)), bt);
        mx = fmaxf(mx, g);
    }
    out_pts[((size_t)b * CC + c) * SS + s] = mx;
}

// ---------------------------------------------------------------------------
// Output layout: new_xyz (B,S,3) flat, then new_points (B,C,S) flat.
// ---------------------------------------------------------------------------
extern "C" void kernel_launch(void* const* d_in, const int* in_sizes, int n_in,
                              void* d_out, int out_size)
{
    const float* xyz    = (const float*)d_in[0];
    const float* points = (const float*)d_in[1];
    const float* alpha  = (const float*)d_in[2];
    const float* beta   = (const float*)d_in[3];

    float* out     = (float*)d_out;
    float* out_xyz = out;
    float* out_pts = out + (size_t)BB * SS * 3;

    cudaFuncSetAttribute(fps_kernel, cudaFuncAttributeMaxDynamicSharedMemorySize,
                         3 * NN * (int)sizeof(float));
    fps_kernel<<<BB, FT, 3 * NN * sizeof(float)>>>(xyz);
    group_kernel<<<dim3(SS, BB), 128>>>(xyz, points, alpha, beta, out_xyz, out_pts);
}

// round 4
// speedup vs baseline: 1.9869x; 1.1132x over previous
#include <cuda_runtime.h>
#include <cstddef>

#define BB 4
#define NN 8192
#define CC 128
#define SS 2048
#define KK 32
#define FT 512          // FPS threads
#define PT 16           // points per thread (512*16 = 8192)
#define NPAIR (PT/2)

typedef unsigned long long u64;

__device__ int g_fps_idx[BB * SS];

// ---- packed f32x2 helpers (each half is an independent IEEE f32 rn op) ----
__device__ __forceinline__ u64 f2add(u64 a, u64 b) {
    u64 d; asm("add.rn.f32x2 %0, %1, %2;" : "=l"(d) : "l"(a), "l"(b)); return d;
}
__device__ __forceinline__ u64 f2mul(u64 a, u64 b) {
    u64 d; asm("mul.rn.f32x2 %0, %1, %2;" : "=l"(d) : "l"(a), "l"(b)); return d;
}
__device__ __forceinline__ u64 f2pack(float lo, float hi) {
    u64 d; asm("mov.b64 %0, {%1, %2};" : "=l"(d) : "f"(lo), "f"(hi)); return d;
}
__device__ __forceinline__ void f2unpack(u64 v, float& lo, float& hi) {
    asm("mov.b64 {%0, %1}, %2;" : "=f"(lo), "=f"(hi) : "l"(v));
}

// ---------------------------------------------------------------------------
// FPS: one CTA per batch, 512 threads, 16 points/thread register-resident.
// Distance update uses packed f32x2 (bit-exact to the unfused scalar form:
// d = ((dx*dx + dy*dy) + dz*dz), dx = px + (-cx)).
// Argmax: value-only reductions (REDUX on float bits, monotone for d >= 0);
// only threads matching the block max run the first-index scan and publish
// via shared atomicMin (smallest global index wins = reference tie-break).
// ---------------------------------------------------------------------------
__global__ __launch_bounds__(FT, 1) void fps_kernel(const float* __restrict__ xyz)
{
    const int b = blockIdx.x;
    const int t = threadIdx.x;
    const int lane = t & 31;
    const int w = t >> 5;

    extern __shared__ float sh[];
    float* sx = sh;
    float* sy = sh + NN;
    float* sz = sh + 2 * NN;

    __shared__ unsigned rk[16];   // per-warp max value bits
    __shared__ int s_far[2];      // double-buffered winning index

    const float* base = xyz + (size_t)b * NN * 3;

    u64 pX[NPAIR], pY[NPAIR], pZ[NPAIR];
    float pd[PT];

#pragma unroll
    for (int j = 0; j < PT; j++) {
        const int i = t * PT + j;
        const float x = base[i * 3 + 0];
        const float y = base[i * 3 + 1];
        const float z = base[i * 3 + 2];
        sx[i] = x; sy[i] = y; sz[i] = z;
        pd[j] = 1e10f;
    }
#pragma unroll
    for (int jp = 0; jp < NPAIR; jp++) {
        const int i0 = t * PT + 2 * jp;
        pX[jp] = f2pack(sx[i0], sx[i0 + 1]);
        pY[jp] = f2pack(sy[i0], sy[i0 + 1]);
        pZ[jp] = f2pack(sz[i0], sz[i0 + 1]);
    }
    if (t == 0) {
        g_fps_idx[b * SS + 0] = 0;
        s_far[0] = 0x7fffffff;
        s_far[1] = 0x7fffffff;
    }
    __syncthreads();

    int far = 0;
    int p = 0;

    for (int step = 1; step < SS; ++step) {
        const float cx = sx[far];
        const float cy = sy[far];
        const float cz = sz[far];
        const u64 ncx = f2pack(-cx, -cx);
        const u64 ncy = f2pack(-cy, -cy);
        const u64 ncz = f2pack(-cz, -cz);

#pragma unroll
        for (int jp = 0; jp < NPAIR; jp++) {
            const u64 dx = f2add(pX[jp], ncx);
            const u64 dy = f2add(pY[jp], ncy);
            const u64 dz = f2add(pZ[jp], ncz);
            const u64 xx = f2mul(dx, dx);
            const u64 yy = f2mul(dy, dy);
            const u64 zz = f2mul(dz, dz);
            const u64 d  = f2add(f2add(xx, yy), zz);
            float dlo, dhi;
            f2unpack(d, dlo, dhi);
            pd[2 * jp]     = fminf(pd[2 * jp],     dlo);
            pd[2 * jp + 1] = fminf(pd[2 * jp + 1], dhi);
        }

        // per-thread max via tree (good ILP); distances are >= 0
        float m01[8];
#pragma unroll
        for (int j = 0; j < 8; j++) m01[j] = fmaxf(pd[2 * j], pd[2 * j + 1]);
#pragma unroll
        for (int j = 0; j < 4; j++) m01[j] = fmaxf(m01[j], m01[j + 4]);
        const float tv = fmaxf(fmaxf(m01[0], m01[1]), fmaxf(m01[2], m01[3]));

        // warp value-only max (bits: monotone for non-negative floats)
        const unsigned vb = __float_as_uint(tv);
        const unsigned wm = __reduce_max_sync(0xffffffffu, vb);
        if (lane == 0) rk[w] = wm;
        __syncthreads();

        // every warp reduces the 16 warp maxima
        const unsigned k = (lane < 16) ? rk[lane] : 0u;
        const unsigned bm = __reduce_max_sync(0xffffffffu, k);

        if (t == 0) s_far[p ^ 1] = 0x7fffffff;   // reset next step's buffer

        if (vb == bm) {
            // winner thread(s): first local index achieving the max
            int bj = PT - 1;
#pragma unroll
            for (int j = PT - 2; j >= 0; j--)
                if (pd[j] == tv) bj = j;
            atomicMin(&s_far[p], t * PT + bj);
        }
        __syncthreads();

        far = s_far[p];
        if (t == 0) g_fps_idx[b * SS + step] = far;
        p ^= 1;
    }
}

// ---------------------------------------------------------------------------
// Fused ball query + grouping + affine + channel max (unchanged, bit-exact).
// ---------------------------------------------------------------------------
__global__ __launch_bounds__(128) void group_kernel(
    const float* __restrict__ xyz,
    const float* __restrict__ points,
    const float* __restrict__ alpha,
    const float* __restrict__ beta,
    float* __restrict__ out_xyz,
    float* __restrict__ out_pts)
{
    const int s = blockIdx.x;
    const int b = blockIdx.y;
    const int tid = threadIdx.x;

    __shared__ int   s_nbr[KK];
    __shared__ int   s_wc[4];
    __shared__ float s_q[3];

    const int fi = g_fps_idx[b * SS + s];
    const float* xb = xyz + (size_t)b * NN * 3;

    if (tid == 0) {
        s_q[0] = xb[fi * 3 + 0];
        s_q[1] = xb[fi * 3 + 1];
        s_q[2] = xb[fi * 3 + 2];
    }
    __syncthreads();

    const float qx = s_q[0], qy = s_q[1], qz = s_q[2];
    const float q2 = __fadd_rn(__fadd_rn(__fmul_rn(qx, qx), __fmul_rn(qy, qy)),
                               __fmul_rn(qz, qz));
    const float RR = 0.04f;   // f32(0.2 * 0.2)

    int cnt = 0;
    const int lane = tid & 31;
    const int w = tid >> 5;

    for (int base2 = 0; base2 < NN && cnt < KK; base2 += 128) {
        const int i = base2 + tid;
        const float xx = xb[i * 3 + 0];
        const float xy = xb[i * 3 + 1];
        const float xz = xb[i * 3 + 2];
        const float x2 = __fadd_rn(__fadd_rn(__fmul_rn(xx, xx), __fmul_rn(xy, xy)),
                                   __fmul_rn(xz, xz));
        // GEMM-style fma-chain dot (k-order 0,1,2, acc starts at 0):
        const float dt = __fmaf_rn(qz, xz, __fmaf_rn(qy, xy, __fmul_rn(qx, xx)));
        const float sqr = __fsub_rn(__fadd_rn(q2, x2), __fmul_rn(2.0f, dt));
        const bool hit = (sqr <= RR);

        const unsigned m = __ballot_sync(0xffffffffu, hit);
        if (lane == 0) s_wc[w] = __popc(m);
        __syncthreads();

        int before = cnt;
        for (int ww = 0; ww < w; ww++) before += s_wc[ww];
        const int pos = before + __popc(m & ((1u << lane) - 1u));
        if (hit && pos < KK) s_nbr[pos] = i;
        const int tot = s_wc[0] + s_wc[1] + s_wc[2] + s_wc[3];
        __syncthreads();
        cnt += tot;   // uniform across block
    }

    const int cf = (cnt < KK) ? cnt : KK;
    if (tid >= cf && tid < KK) s_nbr[tid] = s_nbr[0];   // pad with first hit
    __syncthreads();

    if (tid < 3) out_xyz[((size_t)b * SS + s) * 3 + tid] = s_q[tid];

    const int c = tid;
    const float a  = alpha[c];
    const float bt = beta[c];
    const float* pb = points + (size_t)b * NN * CC;
    const float anc = pb[(size_t)fi * CC + c];

    float mx = -3.402823466e38f;
#pragma unroll 8
    for (int k = 0; k < KK; k++) {
        const float v = pb[(size_t)s_nbr[k] * CC + c];
        const float g = __fadd_rn(__fmul_rn(a, __fsub_rn(v, anc)), bt);
        mx = fmaxf(mx, g);
    }
    out_pts[((size_t)b * CC + c) * SS + s] = mx;
}

// ---------------------------------------------------------------------------
// Output layout: new_xyz (B,S,3) flat, then new_points (B,C,S) flat.
// ---------------------------------------------------------------------------
extern "C" void kernel_launch(void* const* d_in, const int* in_sizes, int n_in,
                              void* d_out, int out_size)
{
    const float* xyz    = (const float*)d_in[0];
    const float* points = (const float*)d_in[1];
    const float* alpha  = (const float*)d_in[2];
    const float* beta   = (const float*)d_in[3];

    float* out     = (float*)d_out;
    float* out_xyz = out;
    float* out_pts = out + (size_t)BB * SS * 3;

    cudaFuncSetAttribute(fps_kernel, cudaFuncAttributeMaxDynamicSharedMemorySize,
                         3 * NN * (int)sizeof(float));
    fps_kernel<<<BB, FT, 3 * NN * sizeof(float)>>>(xyz);
    group_kernel<<<dim3(SS, BB), 128>>>(xyz, points, alpha, beta, out_xyz, out_pts);
}

// round 5
// speedup vs baseline: 2.8966x; 1.4578x over previous
#include <cuda_runtime.h>
#include <cstddef>

#define BB 4
#define NN 8192
#define CC 128
#define SS 2048
#define KK 32

#define G   4            // CTAs per cluster (per batch)
#define FTC 128          // threads per FPS CTA
#define PPC (NN / G)     // 2048 points per CTA
#define PTT (PPC / FTC)  // 16 points per thread
#define NP2 (PTT / 2)    // 8 packed pairs
#define WPC (FTC / 32)   // 4 warps per CTA
#define NKEYS (G * WPC)  // 16 warp keys per step

typedef unsigned long long u64;

__device__ int g_fps_idx[BB * SS];

// ---- packed f32x2 helpers (each half is an independent IEEE f32 rn op) ----
__device__ __forceinline__ u64 f2add(u64 a, u64 b) {
    u64 d; asm("add.rn.f32x2 %0, %1, %2;" : "=l"(d) : "l"(a), "l"(b)); return d;
}
__device__ __forceinline__ u64 f2mul(u64 a, u64 b) {
    u64 d; asm("mul.rn.f32x2 %0, %1, %2;" : "=l"(d) : "l"(a), "l"(b)); return d;
}
__device__ __forceinline__ u64 f2pack(float lo, float hi) {
    u64 d; asm("mov.b64 %0, {%1, %2};" : "=l"(d) : "f"(lo), "f"(hi)); return d;
}
__device__ __forceinline__ void f2unpack(u64 v, float& lo, float& hi) {
    asm("mov.b64 {%0, %1}, %2;" : "=f"(lo), "=f"(hi) : "l"(v));
}

__device__ __forceinline__ unsigned smem_u32(const void* p) {
    unsigned a;
    asm("{ .reg .u64 t; cvta.to.shared.u64 t, %1; cvt.u32.u64 %0, t; }" : "=r"(a) : "l"(p));
    return a;
}
__device__ __forceinline__ unsigned cluster_rank() {
    unsigned r; asm("mov.u32 %0, %%cluster_ctarank;" : "=r"(r)); return r;
}
__device__ __forceinline__ unsigned mapa_u32(unsigned laddr, unsigned rank) {
    unsigned r; asm("mapa.shared::cluster.u32 %0, %1, %2;" : "=r"(r) : "r"(laddr), "r"(rank));
    return r;
}
__device__ __forceinline__ void st_cluster_u64(unsigned addr, u64 v) {
    asm volatile("st.shared::cluster.b64 [%0], %1;" :: "r"(addr), "l"(v) : "memory");
}
__device__ __forceinline__ void arrive_cluster(unsigned addr) {
    asm volatile("mbarrier.arrive.shared::cluster.b64 _, [%0];" :: "r"(addr) : "memory");
}
__device__ __forceinline__ void mbar_init(unsigned addr, unsigned cnt) {
    asm volatile("mbarrier.init.shared.b64 [%0], %1;" :: "r"(addr), "r"(cnt) : "memory");
}
// acquire at CLUSTER scope (arrivals come from peer CTAs)
__device__ __forceinline__ void mbar_wait_cluster(unsigned addr, unsigned parity) {
    unsigned done;
    asm volatile(
        "{\n\t.reg .pred p;\n\t"
        "mbarrier.try_wait.parity.acquire.cluster.shared::cta.b64 p, [%1], %2;\n\t"
        "selp.b32 %0, 1, 0, p;\n\t}"
        : "=r"(done) : "r"(addr), "r"(parity) : "memory");
    if (!done) {
        asm volatile(
            "{\n\t.reg .pred P1;\n\t"
            "W_%=:\n\t"
            "mbarrier.try_wait.parity.acquire.cluster.shared::cta.b64 P1, [%0], %1, 0x989680;\n\t"
            "@P1 bra.uni D_%=;\n\t"
            "bra.uni W_%=;\n\t"
            "D_%=:\n\t}"
            :: "r"(addr), "r"(parity) : "memory");
    }
}
__device__ __forceinline__ void cluster_sync() {
    asm volatile("barrier.cluster.arrive.aligned;" ::: "memory");
    asm volatile("barrier.cluster.wait.aligned;" ::: "memory");
}

// ---------------------------------------------------------------------------
// FPS: 4-CTA cluster per batch, 128 threads/CTA, 16 pts/thread in registers.
// Packed f32x2 distance update (bit-exact to scalar unfused form).
// Per step: warp REDUX (value, then min-index among ties) -> lane0 broadcasts
// warp key to all 4 CTAs' DSMEM mailboxes + release-arrive; all threads
// acquire-wait on own mbarrier (16 arrivals); every warp reduces 16 keys.
// No __syncthreads in the loop. Double-buffered mailbox/mbarrier by step
// parity (safe: release-arrive is ordered after the previous read of the
// same buffer, so a peer cannot lap the reader).
// ---------------------------------------------------------------------------
__global__ __launch_bounds__(FTC, 1) __cluster_dims__(G, 1, 1)
void fps_kernel(const float* __restrict__ xyz)
{
    const int b = blockIdx.x / G;
    const unsigned r = cluster_rank();
    const int t = threadIdx.x;
    const int lane = t & 31;
    const int w = t >> 5;

    extern __shared__ float sh[];
    float* sx = sh;
    float* sy = sh + NN;
    float* sz = sh + 2 * NN;

    __shared__ __align__(8) u64 mbox[2][NKEYS];
    __shared__ __align__(8) u64 mbar[2];

    const float* base = xyz + (size_t)b * NN * 3;

    // full xyz copy in every CTA's shared (for centroid fetch by global idx)
    for (int i = t; i < NN; i += FTC) {
        sx[i] = base[i * 3 + 0];
        sy[i] = base[i * 3 + 1];
        sz[i] = base[i * 3 + 2];
    }

    if (t == 0) {
        mbar_init(smem_u32(&mbar[0]), NKEYS);
        mbar_init(smem_u32(&mbar[1]), NKEYS);
        if (r == 0) g_fps_idx[b * SS + 0] = 0;
    }
    __syncthreads();
    cluster_sync();   // mbarriers + shared tiles visible before any arrive

    // pack this CTA's slice into registers
    const int gstart = (int)r * PPC + t * PTT;
    u64 pX[NP2], pY[NP2], pZ[NP2];
    float pd[PTT];
#pragma unroll
    for (int jp = 0; jp < NP2; jp++) {
        const int i0 = gstart + 2 * jp;
        pX[jp] = f2pack(sx[i0], sx[i0 + 1]);
        pY[jp] = f2pack(sy[i0], sy[i0 + 1]);
        pZ[jp] = f2pack(sz[i0], sz[i0 + 1]);
        pd[2 * jp] = 1e10f;
        pd[2 * jp + 1] = 1e10f;
    }

    const unsigned my_slot_l = smem_u32(&mbox[0][r * WPC + w]);
    const unsigned mbar0_l   = smem_u32(&mbar[0]);
    const unsigned boxstride = (unsigned)(sizeof(u64) * NKEYS);

    int far = 0;
    unsigned ph[2] = {0u, 0u};

    for (int step = 1; step < SS; ++step) {
        const int buf = step & 1;

        const float cx = sx[far];
        const float cy = sy[far];
        const float cz = sz[far];
        const u64 ncx = f2pack(-cx, -cx);
        const u64 ncy = f2pack(-cy, -cy);
        const u64 ncz = f2pack(-cz, -cz);

#pragma unroll
        for (int jp = 0; jp < NP2; jp++) {
            const u64 dx = f2add(pX[jp], ncx);
            const u64 dy = f2add(pY[jp], ncy);
            const u64 dz = f2add(pZ[jp], ncz);
            const u64 xx = f2mul(dx, dx);
            const u64 yy = f2mul(dy, dy);
            const u64 zz = f2mul(dz, dz);
            const u64 d  = f2add(f2add(xx, yy), zz);
            float dlo, dhi;
            f2unpack(d, dlo, dhi);
            pd[2 * jp]     = fminf(pd[2 * jp],     dlo);
            pd[2 * jp + 1] = fminf(pd[2 * jp + 1], dhi);
        }

        // per-thread max (tree) + first local index achieving it
        float m01[8];
#pragma unroll
        for (int j = 0; j < 8; j++) m01[j] = fmaxf(pd[2 * j], pd[2 * j + 1]);
#pragma unroll
        for (int j = 0; j < 4; j++) m01[j] = fmaxf(m01[j], m01[j + 4]);
        const float tv = fmaxf(fmaxf(m01[0], m01[1]), fmaxf(m01[2], m01[3]));

        int bj = PTT - 1;
#pragma unroll
        for (int j = PTT - 2; j >= 0; j--)
            if (pd[j] == tv) bj = j;
        const unsigned gi = (unsigned)(gstart + bj);

        // warp argmax: REDUX max on value bits (monotone, d >= 0),
        // then REDUX min on index among value-ties (= first-index tie-break)
        const unsigned vb = __float_as_uint(tv);
        const unsigned wm = __reduce_max_sync(0xffffffffu, vb);
        const unsigned wi = __reduce_min_sync(0xffffffffu, (vb == wm) ? gi : 0xffffffffu);

        // lane0 broadcasts warp key to every CTA's mailbox + arrives
        if (lane == 0) {
            const u64 key = ((u64)wm << 32) | wi;
            const unsigned slot_off = my_slot_l + (unsigned)buf * boxstride;
            const unsigned bar_off  = mbar0_l + (unsigned)buf * 8u;
#pragma unroll
            for (unsigned c = 0; c < G; c++) {
                st_cluster_u64(mapa_u32(slot_off, c), key);
                arrive_cluster(mapa_u32(bar_off, c));
            }
        }

        // wait for all 16 warp keys, then reduce them redundantly per warp
        mbar_wait_cluster(mbar0_l + (unsigned)buf * 8u, ph[buf]);
        ph[buf] ^= 1u;

        const u64 k = mbox[buf][lane & (NKEYS - 1)];   // lanes 16..31 mirror 0..15
        const unsigned hi = (unsigned)(k >> 32);
        const unsigned bm = __reduce_max_sync(0xffffffffu, hi);
        const unsigned fm = __reduce_min_sync(0xffffffffu,
                                              (hi == bm) ? (unsigned)k : 0xffffffffu);
        far = (int)fm;

        if (r == 0 && t == 0) g_fps_idx[b * SS + step] = far;
    }
}

// ---------------------------------------------------------------------------
// Fused ball query + grouping + affine + channel max (unchanged, bit-exact).
// ---------------------------------------------------------------------------
__global__ __launch_bounds__(128) void group_kernel(
    const float* __restrict__ xyz,
    const float* __restrict__ points,
    const float* __restrict__ alpha,
    const float* __restrict__ beta,
    float* __restrict__ out_xyz,
    float* __restrict__ out_pts)
{
    const int s = blockIdx.x;
    const int b = blockIdx.y;
    const int tid = threadIdx.x;

    __shared__ int   s_nbr[KK];
    __shared__ int   s_wc[4];
    __shared__ float s_q[3];

    const int fi = g_fps_idx[b * SS + s];
    const float* xb = xyz + (size_t)b * NN * 3;

    if (tid == 0) {
        s_q[0] = xb[fi * 3 + 0];
        s_q[1] = xb[fi * 3 + 1];
        s_q[2] = xb[fi * 3 + 2];
    }
    __syncthreads();

    const float qx = s_q[0], qy = s_q[1], qz = s_q[2];
    const float q2 = __fadd_rn(__fadd_rn(__fmul_rn(qx, qx), __fmul_rn(qy, qy)),
                               __fmul_rn(qz, qz));
    const float RR = 0.04f;   // f32(0.2 * 0.2)

    int cnt = 0;
    const int lane = tid & 31;
    const int w = tid >> 5;

    for (int base2 = 0; base2 < NN && cnt < KK; base2 += 128) {
        const int i = base2 + tid;
        const float xx = xb[i * 3 + 0];
        const float xy = xb[i * 3 + 1];
        const float xz = xb[i * 3 + 2];
        const float x2 = __fadd_rn(__fadd_rn(__fmul_rn(xx, xx), __fmul_rn(xy, xy)),
                                   __fmul_rn(xz, xz));
        const float dt = __fmaf_rn(qz, xz, __fmaf_rn(qy, xy, __fmul_rn(qx, xx)));
        const float sqr = __fsub_rn(__fadd_rn(q2, x2), __fmul_rn(2.0f, dt));
        const bool hit = (sqr <= RR);

        const unsigned m = __ballot_sync(0xffffffffu, hit);
        if (lane == 0) s_wc[w] = __popc(m);
        __syncthreads();

        int before = cnt;
        for (int ww = 0; ww < w; ww++) before += s_wc[ww];
        const int pos = before + __popc(m & ((1u << lane) - 1u));
        if (hit && pos < KK) s_nbr[pos] = i;
        const int tot = s_wc[0] + s_wc[1] + s_wc[2] + s_wc[3];
        __syncthreads();
        cnt += tot;   // uniform across block
    }

    const int cf = (cnt < KK) ? cnt : KK;
    if (tid >= cf && tid < KK) s_nbr[tid] = s_nbr[0];   // pad with first hit
    __syncthreads();

    if (tid < 3) out_xyz[((size_t)b * SS + s) * 3 + tid] = s_q[tid];

    const int c = tid;
    const float a  = alpha[c];
    const float bt = beta[c];
    const float* pb = points + (size_t)b * NN * CC;
    const float anc = pb[(size_t)fi * CC + c];

    float mx = -3.402823466e38f;
#pragma unroll 8
    for (int k = 0; k < KK; k++) {
        const float v = pb[(size_t)s_nbr[k] * CC + c];
        const float g = __fadd_rn(__fmul_rn(a, __fsub_rn(v, anc)), bt);
        mx = fmaxf(mx, g);
    }
    out_pts[((size_t)b * CC + c) * SS + s] = mx;
}

// ---------------------------------------------------------------------------
// Output layout: new_xyz (B,S,3) flat, then new_points (B,C,S) flat.
// ---------------------------------------------------------------------------
extern "C" void kernel_launch(void* const* d_in, const int* in_sizes, int n_in,
                              void* d_out, int out_size)
{
    const float* xyz    = (const float*)d_in[0];
    const float* points = (const float*)d_in[1];
    const float* alpha  = (const float*)d_in[2];
    const float* beta   = (const float*)d_in[3];

    float* out     = (float*)d_out;
    float* out_xyz = out;
    float* out_pts = out + (size_t)BB * SS * 3;

    cudaFuncSetAttribute(fps_kernel, cudaFuncAttributeMaxDynamicSharedMemorySize,
                         3 * NN * (int)sizeof(float));
    fps_kernel<<<BB * G, FTC, 3 * NN * sizeof(float)>>>(xyz);
    group_kernel<<<dim3(SS, BB), 128>>>(xyz, points, alpha, beta, out_xyz, out_pts);
}

// round 6
// speedup vs baseline: 3.2934x; 1.1370x over previous
#include <cuda_runtime.h>
#include <cstddef>

#define BB 4
#define NN 8192
#define CC 128
#define SS 2048
#define KK 32

#define G   8            // CTAs per cluster (per batch), portable max
#define FTC 128          // threads per FPS CTA
#define PPC (NN / G)     // 1024 points per CTA
#define PTT (PPC / FTC)  // 8 points per thread
#define NP2 (PTT / 2)    // 4 packed pairs
#define WPC (FTC / 32)   // 4 warps per CTA
#define NKEYS (G * WPC)  // 32 warp keys per step (one per lane)

typedef unsigned long long u64;

__device__ int g_fps_idx[BB * SS];

// ---- packed f32x2 helpers (each half is an independent IEEE f32 rn op) ----
__device__ __forceinline__ u64 f2add(u64 a, u64 b) {
    u64 d; asm("add.rn.f32x2 %0, %1, %2;" : "=l"(d) : "l"(a), "l"(b)); return d;
}
__device__ __forceinline__ u64 f2mul(u64 a, u64 b) {
    u64 d; asm("mul.rn.f32x2 %0, %1, %2;" : "=l"(d) : "l"(a), "l"(b)); return d;
}
__device__ __forceinline__ u64 f2pack(float lo, float hi) {
    u64 d; asm("mov.b64 %0, {%1, %2};" : "=l"(d) : "f"(lo), "f"(hi)); return d;
}
__device__ __forceinline__ void f2unpack(u64 v, float& lo, float& hi) {
    asm("mov.b64 {%0, %1}, %2;" : "=f"(lo), "=f"(hi) : "l"(v));
}

__device__ __forceinline__ unsigned smem_u32(const void* p) {
    unsigned a;
    asm("{ .reg .u64 t; cvta.to.shared.u64 t, %1; cvt.u32.u64 %0, t; }" : "=r"(a) : "l"(p));
    return a;
}
__device__ __forceinline__ unsigned cluster_rank() {
    unsigned r; asm("mov.u32 %0, %%cluster_ctarank;" : "=r"(r)); return r;
}
__device__ __forceinline__ unsigned mapa_u32(unsigned laddr, unsigned rank) {
    unsigned r; asm("mapa.shared::cluster.u32 %0, %1, %2;" : "=r"(r) : "r"(laddr), "r"(rank));
    return r;
}
__device__ __forceinline__ void st_cluster_u64(unsigned addr, u64 v) {
    asm volatile("st.shared::cluster.b64 [%0], %1;" :: "r"(addr), "l"(v) : "memory");
}
__device__ __forceinline__ void arrive_cluster(unsigned addr) {
    asm volatile("mbarrier.arrive.shared::cluster.b64 _, [%0];" :: "r"(addr) : "memory");
}
__device__ __forceinline__ void mbar_init(unsigned addr, unsigned cnt) {
    asm volatile("mbarrier.init.shared.b64 [%0], %1;" :: "r"(addr), "r"(cnt) : "memory");
}
// acquire at CLUSTER scope (arrivals come from peer CTAs)
__device__ __forceinline__ void mbar_wait_cluster(unsigned addr, unsigned parity) {
    unsigned done;
    asm volatile(
        "{\n\t.reg .pred p;\n\t"
        "mbarrier.try_wait.parity.acquire.cluster.shared::cta.b64 p, [%1], %2;\n\t"
        "selp.b32 %0, 1, 0, p;\n\t}"
        : "=r"(done) : "r"(addr), "r"(parity) : "memory");
    if (!done) {
        asm volatile(
            "{\n\t.reg .pred P1;\n\t"
            "W_%=:\n\t"
            "mbarrier.try_wait.parity.acquire.cluster.shared::cta.b64 P1, [%0], %1, 0x989680;\n\t"
            "@P1 bra.uni D_%=;\n\t"
            "bra.uni W_%=;\n\t"
            "D_%=:\n\t}"
            :: "r"(addr), "r"(parity) : "memory");
    }
}
__device__ __forceinline__ void cluster_sync() {
    asm volatile("barrier.cluster.arrive.aligned;" ::: "memory");
    asm volatile("barrier.cluster.wait.aligned;" ::: "memory");
}

// ---------------------------------------------------------------------------
// FPS: 8-CTA cluster per batch, 128 threads/CTA, 8 pts/thread in registers.
// Packed f32x2 distance update (bit-exact to scalar unfused form).
// Per step: warp REDUX (max value bits, then min index among value-ties =
// first-index tie-break); lanes 0..7 store the warp key to peer CTA 'lane'
// and release-arrive IN PARALLEL; all threads acquire-wait (32 arrivals);
// every warp reduces 32 mailbox keys (one per lane) with the same REDUX pair.
// No __syncthreads in the loop; mailbox/mbarrier double-buffered by parity.
// ---------------------------------------------------------------------------
__global__ __launch_bounds__(FTC, 1) __cluster_dims__(G, 1, 1)
void fps_kernel(const float* __restrict__ xyz)
{
    const int b = blockIdx.x / G;
    const unsigned r = cluster_rank();
    const int t = threadIdx.x;
    const int lane = t & 31;
    const int w = t >> 5;

    extern __shared__ float sh[];
    float* sx = sh;
    float* sy = sh + NN;
    float* sz = sh + 2 * NN;

    __shared__ __align__(8) u64 mbox[2][NKEYS];
    __shared__ __align__(8) u64 mbar[2];

    const float* base = xyz + (size_t)b * NN * 3;

    // full xyz copy in every CTA's shared (for centroid fetch by global idx)
    for (int i = t; i < NN; i += FTC) {
        sx[i] = base[i * 3 + 0];
        sy[i] = base[i * 3 + 1];
        sz[i] = base[i * 3 + 2];
    }

    if (t == 0) {
        mbar_init(smem_u32(&mbar[0]), NKEYS);
        mbar_init(smem_u32(&mbar[1]), NKEYS);
        if (r == 0) g_fps_idx[b * SS + 0] = 0;
    }
    __syncthreads();
    cluster_sync();   // mbarriers + shared tiles visible before any arrive

    // pack this CTA's slice into registers
    const int gstart = (int)r * PPC + t * PTT;
    u64 pX[NP2], pY[NP2], pZ[NP2];
    float pd[PTT];
#pragma unroll
    for (int jp = 0; jp < NP2; jp++) {
        const int i0 = gstart + 2 * jp;
        pX[jp] = f2pack(sx[i0], sx[i0 + 1]);
        pY[jp] = f2pack(sy[i0], sy[i0 + 1]);
        pZ[jp] = f2pack(sz[i0], sz[i0 + 1]);
        pd[2 * jp] = 1e10f;
        pd[2 * jp + 1] = 1e10f;
    }

    const unsigned my_slot_l = smem_u32(&mbox[0][r * WPC + w]);
    const unsigned mbar0_l   = smem_u32(&mbar[0]);
    const unsigned boxstride = (unsigned)(sizeof(u64) * NKEYS);

    int far = 0;
    unsigned ph[2] = {0u, 0u};

    for (int step = 1; step < SS; ++step) {
        const int buf = step & 1;

        const float cx = sx[far];
        const float cy = sy[far];
        const float cz = sz[far];
        const u64 ncx = f2pack(-cx, -cx);
        const u64 ncy = f2pack(-cy, -cy);
        const u64 ncz = f2pack(-cz, -cz);

#pragma unroll
        for (int jp = 0; jp < NP2; jp++) {
            const u64 dx = f2add(pX[jp], ncx);
            const u64 dy = f2add(pY[jp], ncy);
            const u64 dz = f2add(pZ[jp], ncz);
            const u64 xx = f2mul(dx, dx);
            const u64 yy = f2mul(dy, dy);
            const u64 zz = f2mul(dz, dz);
            const u64 d  = f2add(f2add(xx, yy), zz);
            float dlo, dhi;
            f2unpack(d, dlo, dhi);
            pd[2 * jp]     = fminf(pd[2 * jp],     dlo);
            pd[2 * jp + 1] = fminf(pd[2 * jp + 1], dhi);
        }

        // per-thread max (tree) + first local index achieving it
        float m01[4];
#pragma unroll
        for (int j = 0; j < 4; j++) m01[j] = fmaxf(pd[2 * j], pd[2 * j + 1]);
        const float tv = fmaxf(fmaxf(m01[0], m01[1]), fmaxf(m01[2], m01[3]));

        int bj = PTT - 1;
#pragma unroll
        for (int j = PTT - 2; j >= 0; j--)
            if (pd[j] == tv) bj = j;
        const unsigned gi = (unsigned)(gstart + bj);

        // warp argmax: REDUX max on value bits (monotone, d >= 0),
        // then REDUX min on index among value-ties (= first-index tie-break)
        const unsigned vb = __float_as_uint(tv);
        const unsigned wm = __reduce_max_sync(0xffffffffu, vb);
        const unsigned wi = __reduce_min_sync(0xffffffffu, (vb == wm) ? gi : 0xffffffffu);

        // lanes 0..G-1 broadcast the (warp-uniform) key to peer 'lane' in parallel
        {
            const u64 key = ((u64)wm << 32) | wi;
            const unsigned slot_off = my_slot_l + (unsigned)buf * boxstride;
            const unsigned bar_off  = mbar0_l + (unsigned)buf * 8u;
            if (lane < G) {
                st_cluster_u64(mapa_u32(slot_off, (unsigned)lane), key);
                arrive_cluster(mapa_u32(bar_off, (unsigned)lane));
            }
        }

        // wait for all 32 warp keys, then reduce them redundantly per warp
        mbar_wait_cluster(mbar0_l + (unsigned)buf * 8u, ph[buf]);
        ph[buf] ^= 1u;

        const u64 k = mbox[buf][lane];   // one key per lane
        const unsigned hi = (unsigned)(k >> 32);
        const unsigned bm = __reduce_max_sync(0xffffffffu, hi);
        const unsigned fm = __reduce_min_sync(0xffffffffu,
                                              (hi == bm) ? (unsigned)k : 0xffffffffu);
        far = (int)fm;

        if (r == 0 && t == 0) g_fps_idx[b * SS + step] = far;
    }
}

// ---------------------------------------------------------------------------
// Fused ball query + grouping + affine + channel max (unchanged, bit-exact).
// ---------------------------------------------------------------------------
__global__ __launch_bounds__(128) void group_kernel(
    const float* __restrict__ xyz,
    const float* __restrict__ points,
    const float* __restrict__ alpha,
    const float* __restrict__ beta,
    float* __restrict__ out_xyz,
    float* __restrict__ out_pts)
{
    const int s = blockIdx.x;
    const int b = blockIdx.y;
    const int tid = threadIdx.x;

    __shared__ int   s_nbr[KK];
    __shared__ int   s_wc[4];
    __shared__ float s_q[3];

    const int fi = g_fps_idx[b * SS + s];
    const float* xb = xyz + (size_t)b * NN * 3;

    if (tid == 0) {
        s_q[0] = xb[fi * 3 + 0];
        s_q[1] = xb[fi * 3 + 1];
        s_q[2] = xb[fi * 3 + 2];
    }
    __syncthreads();

    const float qx = s_q[0], qy = s_q[1], qz = s_q[2];
    const float q2 = __fadd_rn(__fadd_rn(__fmul_rn(qx, qx), __fmul_rn(qy, qy)),
                               __fmul_rn(qz, qz));
    const float RR = 0.04f;   // f32(0.2 * 0.2)

    int cnt = 0;
    const int lane = tid & 31;
    const int w = tid >> 5;

    for (int base2 = 0; base2 < NN && cnt < KK; base2 += 128) {
        const int i = base2 + tid;
        const float xx = xb[i * 3 + 0];
        const float xy = xb[i * 3 + 1];
        const float xz = xb[i * 3 + 2];
        const float x2 = __fadd_rn(__fadd_rn(__fmul_rn(xx, xx), __fmul_rn(xy, xy)),
                                   __fmul_rn(xz, xz));
        const float dt = __fmaf_rn(qz, xz, __fmaf_rn(qy, xy, __fmul_rn(qx, xx)));
        const float sqr = __fsub_rn(__fadd_rn(q2, x2), __fmul_rn(2.0f, dt));
        const bool hit = (sqr <= RR);

        const unsigned m = __ballot_sync(0xffffffffu, hit);
        if (lane == 0) s_wc[w] = __popc(m);
        __syncthreads();

        int before = cnt;
        for (int ww = 0; ww < w; ww++) before += s_wc[ww];
        const int pos = before + __popc(m & ((1u << lane) - 1u));
        if (hit && pos < KK) s_nbr[pos] = i;
        const int tot = s_wc[0] + s_wc[1] + s_wc[2] + s_wc[3];
        __syncthreads();
        cnt += tot;   // uniform across block
    }

    const int cf = (cnt < KK) ? cnt : KK;
    if (tid >= cf && tid < KK) s_nbr[tid] = s_nbr[0];   // pad with first hit
    __syncthreads();

    if (tid < 3) out_xyz[((size_t)b * SS + s) * 3 + tid] = s_q[tid];

    const int c = tid;
    const float a  = alpha[c];
    const float bt = beta[c];
    const float* pb = points + (size_t)b * NN * CC;
    const float anc = pb[(size_t)fi * CC + c];

    float mx = -3.402823466e38f;
#pragma unroll 8
    for (int k = 0; k < KK; k++) {
        const float v = pb[(size_t)s_nbr[k] * CC + c];
        const float g = __fadd_rn(__fmul_rn(a, __fsub_rn(v, anc)), bt);
        mx = fmaxf(mx, g);
    }
    out_pts[((size_t)b * CC + c) * SS + s] = mx;
}

// ---------------------------------------------------------------------------
// Output layout: new_xyz (B,S,3) flat, then new_points (B,C,S) flat.
// ---------------------------------------------------------------------------
extern "C" void kernel_launch(void* const* d_in, const int* in_sizes, int n_in,
                              void* d_out, int out_size)
{
    const float* xyz    = (const float*)d_in[0];
    const float* points = (const float*)d_in[1];
    const float* alpha  = (const float*)d_in[2];
    const float* beta   = (const float*)d_in[3];

    float* out     = (float*)d_out;
    float* out_xyz = out;
    float* out_pts = out + (size_t)BB * SS * 3;

    cudaFuncSetAttribute(fps_kernel, cudaFuncAttributeMaxDynamicSharedMemorySize,
                         3 * NN * (int)sizeof(float));
    fps_kernel<<<BB * G, FTC, 3 * NN * sizeof(float)>>>(xyz);
    group_kernel<<<dim3(SS, BB), 128>>>(xyz, points, alpha, beta, out_xyz, out_pts);
}